// round 11
// baseline (speedup 1.0000x reference)
#include <cuda_runtime.h>

// Not-a-knot cubic spline upsample, 512 x 8192 fp32 -> 512 x 32768 fp32.
// [1,4,1] tridiagonal inverse = exponential Green's function (lam = sqrt(3)-2)
// composed with the 6*[1,-2,1] rhs into a 17-tap FIR on y -> M is LOCAL.
//
// step = 8191/32767: point m of chunk cg lies in interval cg-1 iff
// 8191*m < 3*cg (exact integer predicate) -> static warp-uniform A/B patterns.
// (y,M) stored as float2 by knot slot (slot s = knot kbase-1+s); each thread
// evaluates 2 consecutive chunks, sharing 2 LDS.128 knot loads and 3 interval
// coefficient sets between them.

#define W_DIM  8192
#define NTHR   256
#define TILE_I 1024
#define KT     8
#define SYN    1056
#define SPN    1026      // knot slots 0..1025 = knots kbase-1 .. kbase+1024

#define LAM   (-0.26794919243112270647f)   // sqrt(3) - 2
#define ACOEF (0.28867513459481288225f)    // 1 / (2*sqrt(3))

__global__ __launch_bounds__(NTHR, 6)
void spline_kernel(const float* __restrict__ x, float* __restrict__ out,
                   int nout, float step) {
    __shared__ __align__(16) float  sy[SYN];
    __shared__ __align__(16) float2 sP[SPN];   // (y, M) per knot slot

    const int tid = threadIdx.x;
    const int n = W_DIM - 4;
    const int row = blockIdx.y;
    const int kbase = blockIdx.x * TILE_I;

    const float* xr = x + (size_t)row * W_DIM;
    float* outr = out + (size_t)row * nout + kbase * 4;

    const int ilo = (kbase >= 16) ? (kbase - 16) : 0;
    int ihi = kbase + TILE_I + 16; if (ihi > W_DIM) ihi = W_DIM;
    const int NY = ihi - ilo;

    // ---- load y slice (+halo), aligned float4; init ghost slots ----
    {
        const float4* x4 = (const float4*)(xr + ilo);
        float4* sy4 = (float4*)sy;
        for (int v = tid; v < (NY >> 2); v += NTHR) sy4[v] = x4[v];
        if (tid == 0) sP[0] = make_float2(0.f, 0.f);          // knot kbase-1 (ghost in 1st tile)
        if (tid == 1) sP[SPN - 1] = make_float2(0.f, 0.f);    // knot kbase+1024 (ghost in last)
    }
    __syncthreads();

    // ---- interior M via 17-tap symmetric FIR on y -> (y,M) pairs ----
    {
        const float C0 = -4.3923048f;
        const float C[KT] = { 2.7846097f, -0.7461340f, 0.1999261f, -0.0535701f,
                              0.0143541f, -0.0038462f, 0.0010306f, -0.0002761f };
        const int FLO = (ilo == 0) ? 20 : 12;
        const int kfirst = (kbase >= 1) ? (kbase - 1) : 20;   // lowest knot to write
        int ghi = kbase + TILE_I;
        if (ghi > W_DIM - 21) ghi = W_DIM - 21;
        const int nch = ((ghi - (ilo + FLO)) >> 2) + 1;
        for (int c = tid; c < nch; c += NTHR) {
            const int li0 = FLO + 4 * c;                // li0 % 4 == 0
            float win[20];                              // y[li0-8 .. li0+11]
            const float4* ws = (const float4*)(sy + li0 - 8);
            #pragma unroll
            for (int v = 0; v < 5; ++v) ((float4*)win)[v] = ws[v];
            #pragma unroll
            for (int m = 0; m < 4; ++m) {
                float acc = C0 * win[8 + m];
                #pragma unroll
                for (int k = 1; k <= KT; ++k)
                    acc = fmaf(C[k - 1], win[8 + m - k] + win[8 + m + k], acc);
                const int gi = ilo + li0 + m;
                if (gi >= kfirst && gi <= ghi)
                    sP[gi - kbase + 1] = make_float2(win[8 + m], acc);
            }
        }
    }

    // ---- left edge (row-start tile): exact M[0..19] via Green sums ----
    if (ilo == 0 && tid < 20) {
        const float M1 = sy[2] - 2.f * sy[1] + sy[0];
        float SL = 0.f, lp = LAM;
        #pragma unroll 4
        for (int j = 0; j < 24; ++j) {
            float b = 6.f * (sy[j + 3] - 2.f * sy[j + 2] + sy[j + 1]);
            if (j == 0) b -= M1;
            SL = fmaf(lp, b, SL);
            lp *= LAM;
        }
        float Mv;
        if (tid == 1) {
            Mv = M1;
        } else {
            const int jj = (tid == 0) ? 0 : tid - 2;
            float acc = 0.f, p = 1.f;
            #pragma unroll 4
            for (int d = 0; d <= 12; ++d) {
                const int j = jj - d;
                if (j >= 0) {
                    float b = 6.f * (sy[j + 3] - 2.f * sy[j + 2] + sy[j + 1]);
                    if (j == 0) b -= M1;
                    acc = fmaf(p, b, acc);
                }
                p *= LAM;
            }
            p = LAM;
            #pragma unroll 4
            for (int d = 1; d <= 12; ++d) {
                const int j = jj + d;                   // always < n
                float b = 6.f * (sy[j + 3] - 2.f * sy[j + 2] + sy[j + 1]);
                acc = fmaf(p, b, acc);
                p *= LAM;
            }
            float pw = LAM;                             // lam^{jj+1}
            for (int s = 0; s < jj; ++s) pw *= LAM;
            acc -= pw * SL;
            Mv = ACOEF * acc;
            if (tid == 0) Mv = 2.f * M1 - Mv;
        }
        sP[tid + 1] = make_float2(sy[tid], Mv);         // knot tid (kbase == 0)
    }

    // ---- right edge (row-end tile): exact M[W-20..W-1] ----
    if (kbase + TILE_I == W_DIM && tid >= 32 && tid < 52) {
        const int t = tid - 32;
        const int gi = W_DIM - 20 + t;
        const int lW = W_DIM - ilo;
        const float Mn2 = sy[lW - 1] - 2.f * sy[lW - 2] + sy[lW - 3];
        float SR = 0.f, lp = LAM;
        #pragma unroll 4
        for (int m = 0; m < 24; ++m) {
            const int j = n - 1 - m;
            float b = 6.f * (sy[j + 3 - ilo] - 2.f * sy[j + 2 - ilo] + sy[j + 1 - ilo]);
            if (j == n - 1) b -= Mn2;
            SR = fmaf(lp, b, SR);
            lp *= LAM;
        }
        float Mv;
        if (t == 18) {
            Mv = Mn2;                                   // gi == W-2
        } else {
            const int jj = (t == 19) ? (n - 1) : (gi - 2);
            float acc = 0.f, p = 1.f;
            #pragma unroll 4
            for (int d = 0; d <= 12; ++d) {
                const int j = jj - d;                   // always >= 0
                float b = 6.f * (sy[j + 3 - ilo] - 2.f * sy[j + 2 - ilo] + sy[j + 1 - ilo]);
                if (j == n - 1) b -= Mn2;
                acc = fmaf(p, b, acc);
                p *= LAM;
            }
            p = LAM;
            #pragma unroll 4
            for (int d = 1; d <= 12; ++d) {
                const int j = jj + d;
                if (j < n) {
                    float b = 6.f * (sy[j + 3 - ilo] - 2.f * sy[j + 2 - ilo] + sy[j + 1 - ilo]);
                    acc = fmaf(p, b, acc);
                }
                p *= LAM;
            }
            float pw = LAM;                             // lam^{n-jj}
            for (int s = 0; s < n - 1 - jj; ++s) pw *= LAM;
            acc -= pw * SR;
            Mv = ACOEF * acc;
            if (t == 19) Mv = 2.f * Mn2 - Mv;
        }
        sP[gi - kbase + 1] = make_float2(sy[gi - ilo], Mv);
    }
    __syncthreads();

    // ---- evaluate: 2 consecutive chunks per thread per group ----
    {
        float4* out4 = (float4*)outr;
        const float4* p4 = (const float4*)sP;
        #pragma unroll
        for (int g = 0; g < 2; ++g) {
            const int gl = 2 * tid + g * 512;           // first chunk of pair
            const float4 v0 = p4[tid + g * 256];        // slots gl, gl+1
            const float4 v1 = p4[tid + g * 256 + 1];    // slots gl+2, gl+3
            const float ky0 = v0.x, km0 = v0.y, ky1 = v0.z, km1 = v0.w;
            const float ky2 = v1.x, km2 = v1.y, ky3 = v1.z, km3 = v1.w;

            // interval coefficient sets j=0..2 (interval = knot slot gl+j)
            float Sx[3], Sy[3], Sz[3], Sw[3];
            Sx[0] = ky0;
            Sy[0] = fmaf(fmaf(2.f, km0, km1), -(1.f / 6.f), ky1 - ky0);
            Sz[0] = 0.5f * km0;
            Sw[0] = (km1 - km0) * (1.f / 6.f);
            Sx[1] = ky1;
            Sy[1] = fmaf(fmaf(2.f, km1, km2), -(1.f / 6.f), ky2 - ky1);
            Sz[1] = 0.5f * km1;
            Sw[1] = (km2 - km1) * (1.f / 6.f);
            Sx[2] = ky2;
            Sy[2] = fmaf(fmaf(2.f, km2, km3), -(1.f / 6.f), ky3 - ky2);
            Sz[2] = 0.5f * km2;
            Sw[2] = (km3 - km2) * (1.f / 6.f);

            #pragma unroll
            for (int k = 0; k < 2; ++k) {               // chunk k: A=S[k], B=S[k+1]
                const int cl = gl + k;
                const int cg = kbase + cl;
                const float q0f = (float)(4 * cg);      // exact
                const float fi0 = (float)(cg - 1);      // exact

                #define FQ(m)   ((q0f + (float)(m)) * step)
                #define TA(m)   (FQ(m) - fi0)           // Sterbenz-exact
                #define EVP(j,t) fmaf((t), fmaf((t), fmaf((t), Sw[j], Sz[j]), Sy[j]), Sx[j])

                const int cg3 = 3 * cg;
                float4 r;
                if (cg3 > 16382) {                      // cg >= 5461
                    if (cg == W_DIM - 1) {              // AAAA (t3 = 1 exactly)
                        r.x = EVP(k, TA(0)); r.y = EVP(k, TA(1));
                        r.z = EVP(k, TA(2)); r.w = EVP(k, TA(3));
                    } else {                            // A A A B
                        r.x = EVP(k, TA(0)); r.y = EVP(k, TA(1));
                        r.z = EVP(k, TA(2)); r.w = EVP(k + 1, TA(3) - 1.0f);
                    }
                } else if (cg3 > 8191) {                // A A B B
                    r.x = EVP(k, TA(0));                r.y = EVP(k, TA(1));
                    r.z = EVP(k + 1, TA(2) - 1.0f);     r.w = EVP(k + 1, TA(3) - 1.0f);
                } else if (cg3 > 0) {                   // A B B B
                    r.x = EVP(k, TA(0));                r.y = EVP(k + 1, TA(1) - 1.0f);
                    r.z = EVP(k + 1, TA(2) - 1.0f);     r.w = EVP(k + 1, TA(3) - 1.0f);
                } else {                                // cg == 0: all interval 0
                    r.x = EVP(k + 1, FQ(0)); r.y = EVP(k + 1, FQ(1));
                    r.z = EVP(k + 1, FQ(2)); r.w = EVP(k + 1, FQ(3));
                }
                #undef FQ
                #undef TA
                #undef EVP
                out4[cl] = r;
            }
        }
    }
}

extern "C" void kernel_launch(void* const* d_in, const int* in_sizes, int n_in,
                              void* d_out, int out_size) {
    const float* x = (const float*)d_in[0];
    float* out = (float*)d_out;

    const int B = in_sizes[0] / W_DIM;               // 512
    const int nout = out_size / B;                   // 32768
    const float step = (float)((double)(W_DIM - 1) / (double)(nout - 1));

    dim3 grid(W_DIM / TILE_I, B);                    // 8 x 512 = 4096 CTAs
    spline_kernel<<<grid, NTHR>>>(x, out, nout, step);
}